// round 1
// baseline (speedup 1.0000x reference)
#include <cuda_runtime.h>
#include <math.h>

#define B_   2
#define S_   2048
#define D_   1024
#define H_   16
#define HD_  64
#define GLB  16
#define HALFW 32   // WINDOW // 2

#define MTOT (B_*S_)   // 4096

// ---------------- scratch (static device globals; no allocs allowed) ----------
__device__ float g_Q[MTOT * D_];
__device__ float g_K[MTOT * D_];
__device__ float g_V[MTOT * D_];
__device__ float g_ctx[MTOT * D_];

// ---------------- SGEMM: C[M,N] = A[M,K] @ W[N,K]^T + bias[N] -----------------
// 128x128 tile, BK=8, 256 threads, 8x8 per-thread microtile.
// Requires M%128==0, N%128==0, K%8==0 (true here: 4096,1024,1024).
__global__ __launch_bounds__(256) void gemm_nt_bias(
    const float* __restrict__ A, const float* __restrict__ W,
    const float* __restrict__ bias, float* __restrict__ C,
    int M, int N, int K)
{
    __shared__ float As[8][128];
    __shared__ float Bs[8][128];

    const int tid = threadIdx.x;
    const int bm  = blockIdx.y * 128;
    const int bn  = blockIdx.x * 128;

    // cooperative loads: 2 threads per row, float4 each (128 rows x 8 k)
    const int lr = tid >> 1;
    const int lk = (tid & 1) << 2;
    // compute mapping: 16x16 thread grid, 8x8 each
    const int tr = (tid >> 4) << 3;
    const int tc = (tid & 15) << 3;

    const float* Aptr = A + (size_t)(bm + lr) * K + lk;
    const float* Wptr = W + (size_t)(bn + lr) * K + lk;

    float acc[8][8];
#pragma unroll
    for (int x = 0; x < 8; x++)
#pragma unroll
        for (int y = 0; y < 8; y++) acc[x][y] = 0.f;

    for (int k0 = 0; k0 < K; k0 += 8) {
        float4 a4 = *(const float4*)(Aptr + k0);
        float4 b4 = *(const float4*)(Wptr + k0);
        As[lk + 0][lr] = a4.x; As[lk + 1][lr] = a4.y;
        As[lk + 2][lr] = a4.z; As[lk + 3][lr] = a4.w;
        Bs[lk + 0][lr] = b4.x; Bs[lk + 1][lr] = b4.y;
        Bs[lk + 2][lr] = b4.z; Bs[lk + 3][lr] = b4.w;
        __syncthreads();

#pragma unroll
        for (int kk = 0; kk < 8; kk++) {
            float ra[8], rb[8];
#pragma unroll
            for (int x = 0; x < 8; x++) ra[x] = As[kk][tr + x];
#pragma unroll
            for (int y = 0; y < 8; y++) rb[y] = Bs[kk][tc + y];
#pragma unroll
            for (int x = 0; x < 8; x++)
#pragma unroll
                for (int y = 0; y < 8; y++)
                    acc[x][y] = fmaf(ra[x], rb[y], acc[x][y]);
        }
        __syncthreads();
    }

#pragma unroll
    for (int x = 0; x < 8; x++) {
        float* crow = C + (size_t)(bm + tr + x) * N + bn + tc;
#pragma unroll
        for (int y = 0; y < 8; y++)
            crow[y] = acc[x][y] + bias[bn + tc + y];
    }
}

// ---------------- sparse attention: one block per (b, h, i) row ---------------
// Computes scores for masked columns only, softmax, writes the full attn row
// (zeros outside the mask -- matches exp(-1e9) underflow in the reference),
// and accumulates ctx[b,i,h*64:].
__global__ __launch_bounds__(128) void attn_kernel(
    const float* __restrict__ Q, const float* __restrict__ K,
    const float* __restrict__ V, float* __restrict__ attn /* may be null */,
    float* __restrict__ ctx)
{
    const int i = blockIdx.x;
    const int h = blockIdx.y;
    const int b = blockIdx.z;
    const int tid = threadIdx.x;

    __shared__ __align__(16) float qs[HD_];
    __shared__ float p[S_];
    __shared__ float red[4];
    __shared__ float s_bcast;

    const float* qrow = Q + ((size_t)(b * S_ + i)) * D_ + h * HD_;
    if (tid < HD_) qs[tid] = qrow[tid];

    const bool full = (i < GLB);
    int bandlo = 0, bandhi = -1, cnt;
    if (full) {
        cnt = S_;
    } else {
        bandlo = i - HALFW; if (bandlo < GLB) bandlo = GLB;
        bandhi = i + HALFW; if (bandhi > S_ - 1) bandhi = S_ - 1;
        cnt = GLB + bandhi - bandlo + 1;
    }
    __syncthreads();

    // ---- scores over masked columns ----
    float lmax = -1e30f;
    for (int idx = tid; idx < cnt; idx += 128) {
        const int j = full ? idx : (idx < GLB ? idx : bandlo + idx - GLB);
        const float* krow = K + ((size_t)(b * S_ + j)) * D_ + h * HD_;
        float s = 0.f;
#pragma unroll
        for (int d = 0; d < HD_; d += 4) {
            float4 kv = *(const float4*)(krow + d);
            float4 qv = *(const float4*)(qs + d);
            s = fmaf(qv.x, kv.x, s); s = fmaf(qv.y, kv.y, s);
            s = fmaf(qv.z, kv.z, s); s = fmaf(qv.w, kv.w, s);
        }
        s *= 0.125f;  // 1/sqrt(64)
        p[idx] = s;
        lmax = fmaxf(lmax, s);
    }
    // block max
#pragma unroll
    for (int o = 16; o; o >>= 1) lmax = fmaxf(lmax, __shfl_xor_sync(0xffffffffu, lmax, o));
    if ((tid & 31) == 0) red[tid >> 5] = lmax;
    __syncthreads();
    if (tid == 0) s_bcast = fmaxf(fmaxf(red[0], red[1]), fmaxf(red[2], red[3]));
    __syncthreads();
    const float m = s_bcast;
    __syncthreads();

    // ---- exp + sum ----
    float lsum = 0.f;
    for (int idx = tid; idx < cnt; idx += 128) {
        float e = __expf(p[idx] - m);
        p[idx] = e;
        lsum += e;
    }
#pragma unroll
    for (int o = 16; o; o >>= 1) lsum += __shfl_xor_sync(0xffffffffu, lsum, o);
    if ((tid & 31) == 0) red[tid >> 5] = lsum;
    __syncthreads();
    if (tid == 0) s_bcast = 1.f / (red[0] + red[1] + red[2] + red[3]);
    __syncthreads();
    const float inv = s_bcast;

    // ---- write full attn row (zeros outside mask) ----
    if (attn) {
        float* arow = attn + (((size_t)(b * H_ + h)) * S_ + i) * S_;
        for (int j0 = tid * 4; j0 < S_; j0 += 128 * 4) {
            float4 o4;
            float* op = &o4.x;
#pragma unroll
            for (int u = 0; u < 4; u++) {
                const int j = j0 + u;
                float v = 0.f;
                if (full)            v = p[j] * inv;
                else if (j < GLB)    v = p[j] * inv;
                else if (j >= bandlo && j <= bandhi)
                                     v = p[GLB + j - bandlo] * inv;
                op[u] = v;
            }
            *(float4*)(arow + j0) = o4;
        }
    }

    // ---- ctx = sum_j p_j * v_j  (64 threads, one per head dim) ----
    if (tid < HD_) {
        float acc = 0.f;
        for (int idx = 0; idx < cnt; idx++) {
            const int j = full ? idx : (idx < GLB ? idx : bandlo + idx - GLB);
            acc = fmaf(p[idx], V[((size_t)(b * S_ + j)) * D_ + h * HD_ + tid], acc);
        }
        ctx[((size_t)(b * S_ + i)) * D_ + h * HD_ + tid] = acc * inv;
    }
}

// ------------------------------- launch ---------------------------------------
extern "C" void kernel_launch(void* const* d_in, const int* in_sizes, int n_in,
                              void* d_out, int out_size)
{
    const float* query = (const float*)d_in[0];
    const float* key   = (const float*)d_in[1];
    const float* value = (const float*)d_in[2];
    const float* Wq = (const float*)d_in[3];
    const float* bq = (const float*)d_in[4];
    const float* Wk = (const float*)d_in[5];
    const float* bk = (const float*)d_in[6];
    const float* Wv = (const float*)d_in[7];
    const float* bv = (const float*)d_in[8];
    const float* Wo = (const float*)d_in[9];
    const float* bo = (const float*)d_in[10];

    float* out = (float*)d_out;

    float *Qp, *Kp, *Vp, *Cp;
    cudaGetSymbolAddress((void**)&Qp, g_Q);
    cudaGetSymbolAddress((void**)&Kp, g_K);
    cudaGetSymbolAddress((void**)&Vp, g_V);
    cudaGetSymbolAddress((void**)&Cp, g_ctx);

    const size_t out_elems  = (size_t)B_ * S_ * D_;                 // 4,194,304
    const size_t attn_elems = (size_t)B_ * H_ * S_ * S_;            // 134,217,728
    const bool write_attn = ((size_t)out_size >= out_elems + attn_elems);
    float* attn = write_attn ? (out + out_elems) : nullptr;

    dim3 gg(D_ / 128, MTOT / 128);   // (8, 32)

    gemm_nt_bias<<<gg, 256>>>(query, Wq, bq, Qp, MTOT, D_, D_);
    gemm_nt_bias<<<gg, 256>>>(key,   Wk, bk, Kp, MTOT, D_, D_);
    gemm_nt_bias<<<gg, 256>>>(value, Wv, bv, Vp, MTOT, D_, D_);

    attn_kernel<<<dim3(S_, H_, B_), 128>>>(Qp, Kp, Vp, attn, Cp);

    gemm_nt_bias<<<gg, 256>>>(Cp, Wo, bo, out, MTOT, D_, D_);
}

// round 2
// speedup vs baseline: 1.1340x; 1.1340x over previous
#include <cuda_runtime.h>
#include <math.h>

#define B_   2
#define S_   2048
#define D_   1024
#define H_   16
#define HD_  64
#define GLB  16
#define HALFW 32   // WINDOW // 2

#define MTOT (B_*S_)   // 4096

// ---------------- scratch (static device globals; no allocs allowed) ----------
__device__ float g_Q[MTOT * D_];
__device__ float g_K[MTOT * D_];
__device__ float g_V[MTOT * D_];
__device__ float g_ctx[MTOT * D_];

struct GArgs { const float* A; const float* W; const float* bias; float* C; };

// ---------------- SGEMM: C[M,N] = A[M,K] @ W[N,K]^T + bias[N] -----------------
// 128x128 tile, BK=8, 256 threads, 8x8 per-thread microtile, double-buffered smem.
// Fixed M=4096 (per z-slice grid.y covers it), N=1024, K=1024.
// blockIdx.z selects one of up to 3 GEMMs (batched QKV).
__global__ __launch_bounds__(256, 2) void gemm_nt_bias(
    GArgs g0, GArgs g1, GArgs g2, int K, int N)
{
    GArgs g = (blockIdx.z == 0) ? g0 : ((blockIdx.z == 1) ? g1 : g2);

    __shared__ float As[2][8][128];
    __shared__ float Bs[2][8][128];

    const int tid = threadIdx.x;
    const int bm  = blockIdx.y * 128;
    const int bn  = blockIdx.x * 128;

    const int lr = tid >> 1;          // 0..127
    const int lk = (tid & 1) << 2;    // 0 or 4
    const int tr = (tid >> 4) << 3;   // 0..120
    const int tc = (tid & 15) << 3;   // 0..120

    const float* Aptr = g.A + (size_t)(bm + lr) * K + lk;
    const float* Wptr = g.W + (size_t)(bn + lr) * K + lk;

    float acc[8][8];
#pragma unroll
    for (int x = 0; x < 8; x++)
#pragma unroll
        for (int y = 0; y < 8; y++) acc[x][y] = 0.f;

    // preload first k-tile into buffer 0
    {
        float4 a4 = *(const float4*)(Aptr);
        float4 b4 = *(const float4*)(Wptr);
        As[0][lk + 0][lr] = a4.x; As[0][lk + 1][lr] = a4.y;
        As[0][lk + 2][lr] = a4.z; As[0][lk + 3][lr] = a4.w;
        Bs[0][lk + 0][lr] = b4.x; Bs[0][lk + 1][lr] = b4.y;
        Bs[0][lk + 2][lr] = b4.z; Bs[0][lk + 3][lr] = b4.w;
    }
    __syncthreads();

    int buf = 0;
    for (int k0 = 0; k0 < K; k0 += 8) {
        float4 na, nb;
        const bool more = (k0 + 8 < K);
        if (more) {
            na = *(const float4*)(Aptr + k0 + 8);
            nb = *(const float4*)(Wptr + k0 + 8);
        }
#pragma unroll
        for (int kk = 0; kk < 8; kk++) {
            float4 a0 = *(const float4*)(&As[buf][kk][tr]);
            float4 a1 = *(const float4*)(&As[buf][kk][tr + 4]);
            float4 b0 = *(const float4*)(&Bs[buf][kk][tc]);
            float4 b1 = *(const float4*)(&Bs[buf][kk][tc + 4]);
            float ra[8] = {a0.x,a0.y,a0.z,a0.w,a1.x,a1.y,a1.z,a1.w};
            float rb[8] = {b0.x,b0.y,b0.z,b0.w,b1.x,b1.y,b1.z,b1.w};
#pragma unroll
            for (int x = 0; x < 8; x++)
#pragma unroll
                for (int y = 0; y < 8; y++)
                    acc[x][y] = fmaf(ra[x], rb[y], acc[x][y]);
        }
        if (more) {
            const int nb_ = buf ^ 1;
            As[nb_][lk + 0][lr] = na.x; As[nb_][lk + 1][lr] = na.y;
            As[nb_][lk + 2][lr] = na.z; As[nb_][lk + 3][lr] = na.w;
            Bs[nb_][lk + 0][lr] = nb.x; Bs[nb_][lk + 1][lr] = nb.y;
            Bs[nb_][lk + 2][lr] = nb.z; Bs[nb_][lk + 3][lr] = nb.w;
            __syncthreads();
            buf = nb_;
        }
    }

#pragma unroll
    for (int x = 0; x < 8; x++) {
        float* crow = g.C + (size_t)(bm + tr + x) * N + bn + tc;
        const float* bp = g.bias + bn + tc;
        float4 c0, c1;
        c0.x = acc[x][0] + bp[0]; c0.y = acc[x][1] + bp[1];
        c0.z = acc[x][2] + bp[2]; c0.w = acc[x][3] + bp[3];
        c1.x = acc[x][4] + bp[4]; c1.y = acc[x][5] + bp[5];
        c1.z = acc[x][6] + bp[6]; c1.w = acc[x][7] + bp[7];
        *(float4*)(crow)     = c0;
        *(float4*)(crow + 4) = c1;
    }
}

// ---------------- sparse attention: one block per (b, h, i) row ---------------
// attn buffer is pre-zeroed by cudaMemsetAsync; this kernel only writes the
// nonzero (masked-in) entries, plus ctx.
__global__ __launch_bounds__(128) void attn_kernel(
    const float* __restrict__ Q, const float* __restrict__ K,
    const float* __restrict__ V, float* __restrict__ attn /* may be null */,
    float* __restrict__ ctx)
{
    const int i = blockIdx.x;
    const int h = blockIdx.y;
    const int b = blockIdx.z;
    const int tid = threadIdx.x;

    __shared__ __align__(16) float qs[HD_];
    __shared__ float p[S_];
    __shared__ float red[4];
    __shared__ float s_bcast;
    __shared__ float cxs[HD_];

    const float* qrow = Q + ((size_t)(b * S_ + i)) * D_ + h * HD_;
    if (tid < HD_) qs[tid] = qrow[tid];

    const bool full = (i < GLB);
    int bandlo = 0, bandhi = -1, cnt;
    if (full) {
        cnt = S_;
    } else {
        bandlo = i - HALFW; if (bandlo < GLB) bandlo = GLB;
        bandhi = i + HALFW; if (bandhi > S_ - 1) bandhi = S_ - 1;
        cnt = GLB + bandhi - bandlo + 1;
    }
    __syncthreads();

    // ---- scores over masked columns ----
    float lmax = -1e30f;
    for (int idx = tid; idx < cnt; idx += 128) {
        const int j = full ? idx : (idx < GLB ? idx : bandlo + idx - GLB);
        const float* krow = K + ((size_t)(b * S_ + j)) * D_ + h * HD_;
        float s = 0.f;
#pragma unroll
        for (int d = 0; d < HD_; d += 4) {
            float4 kv = *(const float4*)(krow + d);
            float4 qv = *(const float4*)(qs + d);
            s = fmaf(qv.x, kv.x, s); s = fmaf(qv.y, kv.y, s);
            s = fmaf(qv.z, kv.z, s); s = fmaf(qv.w, kv.w, s);
        }
        s *= 0.125f;  // 1/sqrt(64)
        p[idx] = s;
        lmax = fmaxf(lmax, s);
    }
#pragma unroll
    for (int o = 16; o; o >>= 1) lmax = fmaxf(lmax, __shfl_xor_sync(0xffffffffu, lmax, o));
    if ((tid & 31) == 0) red[tid >> 5] = lmax;
    __syncthreads();
    if (tid == 0) s_bcast = fmaxf(fmaxf(red[0], red[1]), fmaxf(red[2], red[3]));
    __syncthreads();
    const float m = s_bcast;
    __syncthreads();

    // ---- exp + sum ----
    float lsum = 0.f;
    for (int idx = tid; idx < cnt; idx += 128) {
        float e = __expf(p[idx] - m);
        p[idx] = e;
        lsum += e;
    }
#pragma unroll
    for (int o = 16; o; o >>= 1) lsum += __shfl_xor_sync(0xffffffffu, lsum, o);
    if ((tid & 31) == 0) red[tid >> 5] = lsum;
    __syncthreads();
    if (tid == 0) s_bcast = 1.f / (red[0] + red[1] + red[2] + red[3]);
    __syncthreads();
    const float inv = s_bcast;

    // ---- write nonzero attn entries only (rest pre-zeroed) ----
    if (attn) {
        float* arow = attn + (((size_t)(b * H_ + h)) * S_ + i) * S_;
        if (full) {
            for (int j0 = tid * 4; j0 < S_; j0 += 128 * 4) {
                float4 o4;
                o4.x = p[j0 + 0] * inv; o4.y = p[j0 + 1] * inv;
                o4.z = p[j0 + 2] * inv; o4.w = p[j0 + 3] * inv;
                *(float4*)(arow + j0) = o4;
            }
        } else {
            if (tid < GLB) arow[tid] = p[tid] * inv;
            for (int idx = GLB + tid; idx < cnt; idx += 128)
                arow[bandlo + idx - GLB] = p[idx] * inv;
        }
    }

    // ---- ctx = sum_j p_j * v_j  (128 threads: 2-way split over j) ----
    {
        const int d    = tid & 63;
        const int half = tid >> 6;      // 0 or 1
        float acc = 0.f;
        for (int idx = half; idx < cnt; idx += 2) {
            const int j = full ? idx : (idx < GLB ? idx : bandlo + idx - GLB);
            acc = fmaf(p[idx], V[((size_t)(b * S_ + j)) * D_ + h * HD_ + d], acc);
        }
        if (half == 1) cxs[d] = acc;
        __syncthreads();
        if (half == 0)
            ctx[((size_t)(b * S_ + i)) * D_ + h * HD_ + d] = (acc + cxs[d]) * inv;
    }
}

// ------------------------------- launch ---------------------------------------
extern "C" void kernel_launch(void* const* d_in, const int* in_sizes, int n_in,
                              void* d_out, int out_size)
{
    const float* query = (const float*)d_in[0];
    const float* key   = (const float*)d_in[1];
    const float* value = (const float*)d_in[2];
    const float* Wq = (const float*)d_in[3];
    const float* bq = (const float*)d_in[4];
    const float* Wk = (const float*)d_in[5];
    const float* bk = (const float*)d_in[6];
    const float* Wv = (const float*)d_in[7];
    const float* bv = (const float*)d_in[8];
    const float* Wo = (const float*)d_in[9];
    const float* bo = (const float*)d_in[10];

    float* out = (float*)d_out;

    float *Qp, *Kp, *Vp, *Cp;
    cudaGetSymbolAddress((void**)&Qp, g_Q);
    cudaGetSymbolAddress((void**)&Kp, g_K);
    cudaGetSymbolAddress((void**)&Vp, g_V);
    cudaGetSymbolAddress((void**)&Cp, g_ctx);

    const size_t out_elems  = (size_t)B_ * S_ * D_;                 // 4,194,304
    const size_t attn_elems = (size_t)B_ * H_ * S_ * S_;            // 134,217,728
    const bool write_attn = ((size_t)out_size >= out_elems + attn_elems);
    float* attn = write_attn ? (out + out_elems) : nullptr;

    // zero the attn region up front (bulk of it stays zero; attn_kernel
    // scatters only the ~81 nonzero entries per row)
    if (attn)
        cudaMemsetAsync(attn, 0, attn_elems * sizeof(float));

    GArgs gq{query, Wq, bq, Qp};
    GArgs gk{key,   Wk, bk, Kp};
    GArgs gv{value, Wv, bv, Vp};
    GArgs go{Cp,    Wo, bo, out};

    // batched QKV: one launch, 3 z-slices (768 blocks -> better wave packing)
    dim3 gqkv(D_ / 128, MTOT / 128, 3);   // (8, 32, 3)
    gemm_nt_bias<<<gqkv, 256>>>(gq, gk, gv, D_, D_);

    attn_kernel<<<dim3(S_, H_, B_), 128>>>(Qp, Kp, Vp, attn, Cp);

    dim3 gout(D_ / 128, MTOT / 128, 1);
    gemm_nt_bias<<<gout, 256>>>(go, go, go, D_, D_);
}

// round 4
// speedup vs baseline: 2.0532x; 1.8105x over previous
#include <cuda_runtime.h>
#include <cuda_bf16.h>
#include <math.h>
#include <stdint.h>

#define B_   2
#define S_   2048
#define D_   1024
#define H_   16
#define HD_  64
#define GLB  16
#define HALFW 32

#define MTOT (B_*S_)   // 4096

// ---------------- scratch ------------------------------------------------------
__device__ __align__(16) float g_Q[MTOT * D_];
__device__ __align__(16) float g_K[MTOT * D_];
__device__ __align__(16) float g_V[MTOT * D_];
__device__ __align__(16) float g_ctx[MTOT * D_];

// bf16 hi/lo copies
__device__ __align__(16) __nv_bfloat16 g_qh[MTOT * D_], g_ql[MTOT * D_];
__device__ __align__(16) __nv_bfloat16 g_kh[MTOT * D_], g_kl[MTOT * D_];
__device__ __align__(16) __nv_bfloat16 g_vh[MTOT * D_], g_vl[MTOT * D_];
__device__ __align__(16) __nv_bfloat16 g_ch[MTOT * D_], g_cl[MTOT * D_];
__device__ __align__(16) __nv_bfloat16 g_wqh[D_ * D_], g_wql[D_ * D_];
__device__ __align__(16) __nv_bfloat16 g_wkh[D_ * D_], g_wkl[D_ * D_];
__device__ __align__(16) __nv_bfloat16 g_wvh[D_ * D_], g_wvl[D_ * D_];
__device__ __align__(16) __nv_bfloat16 g_woh[D_ * D_], g_wol[D_ * D_];

// ---------------- fp32 -> bf16 hi/lo pre-convert --------------------------------
struct CvtArgs { const float* in; __nv_bfloat16* h; __nv_bfloat16* l; };

__global__ __launch_bounds__(256) void cvt_hilo(
    CvtArgs c0, CvtArgs c1, CvtArgs c2, CvtArgs c3, int n)
{
    CvtArgs c = (blockIdx.z == 0) ? c0 : (blockIdx.z == 1) ? c1 :
                (blockIdx.z == 2) ? c2 : c3;
    const int stride = gridDim.x * blockDim.x * 4;
    for (int i = (blockIdx.x * blockDim.x + threadIdx.x) * 4; i < n; i += stride) {
        float4 v = *(const float4*)(c.in + i);
        __nv_bfloat16 h0 = __float2bfloat16_rn(v.x);
        __nv_bfloat16 h1 = __float2bfloat16_rn(v.y);
        __nv_bfloat16 h2 = __float2bfloat16_rn(v.z);
        __nv_bfloat16 h3 = __float2bfloat16_rn(v.w);
        __nv_bfloat16 l0 = __float2bfloat16_rn(v.x - __bfloat162float(h0));
        __nv_bfloat16 l1 = __float2bfloat16_rn(v.y - __bfloat162float(h1));
        __nv_bfloat16 l2 = __float2bfloat16_rn(v.z - __bfloat162float(h2));
        __nv_bfloat16 l3 = __float2bfloat16_rn(v.w - __bfloat162float(h3));
        uint2 hp, lp;
        hp.x = (uint32_t)__bfloat16_as_ushort(h0) | ((uint32_t)__bfloat16_as_ushort(h1) << 16);
        hp.y = (uint32_t)__bfloat16_as_ushort(h2) | ((uint32_t)__bfloat16_as_ushort(h3) << 16);
        lp.x = (uint32_t)__bfloat16_as_ushort(l0) | ((uint32_t)__bfloat16_as_ushort(l1) << 16);
        lp.y = (uint32_t)__bfloat16_as_ushort(l2) | ((uint32_t)__bfloat16_as_ushort(l3) << 16);
        *(uint2*)(c.h + i) = hp;
        *(uint2*)(c.l + i) = lp;
    }
}

// ---------------- HMMA GEMM: C[M,N] = A[M,K] @ W[N,K]^T + bias ------------------
// bf16x3 split: C = Ah*Bh + Ah*Bl + Al*Bh. Block 128x128x32, 256 threads,
// 8 warps in 2(m) x 4(n), warp tile 64x32, mma.sync.m16n8k16.row.col.
struct GemmB {
    const __nv_bfloat16 *Ah, *Al, *Wh, *Wl;
    const float* bias;
    float* C;
};

#define SROW 40            // padded row length (elements); 80 bytes, 16B-multiple

__device__ __forceinline__ uint32_t lds_u32(const __nv_bfloat16* s, int row, int k) {
    return *(const uint32_t*)((const char*)s + row * (SROW * 2) + k * 2);
}

__device__ __forceinline__ void mma16816(
    float& d0, float& d1, float& d2, float& d3,
    uint32_t a0, uint32_t a1, uint32_t a2, uint32_t a3,
    uint32_t b0, uint32_t b1)
{
    asm volatile(
        "mma.sync.aligned.m16n8k16.row.col.f32.bf16.bf16.f32 "
        "{%0,%1,%2,%3}, {%4,%5,%6,%7}, {%8,%9}, {%0,%1,%2,%3};"
        : "+f"(d0), "+f"(d1), "+f"(d2), "+f"(d3)
        : "r"(a0), "r"(a1), "r"(a2), "r"(a3), "r"(b0), "r"(b1));
}

__global__ __launch_bounds__(256) void gemm_mma(GemmB g0, GemmB g1, GemmB g2)
{
    GemmB g = (blockIdx.z == 0) ? g0 : ((blockIdx.z == 1) ? g1 : g2);

    __shared__ __align__(16) __nv_bfloat16 sAh[128 * SROW];
    __shared__ __align__(16) __nv_bfloat16 sAl[128 * SROW];
    __shared__ __align__(16) __nv_bfloat16 sBh[128 * SROW];
    __shared__ __align__(16) __nv_bfloat16 sBl[128 * SROW];

    const int tid  = threadIdx.x;
    const int wid  = tid >> 5;
    const int lane = tid & 31;
    const int bm = blockIdx.y * 128;
    const int bn = blockIdx.x * 128;
    const int warp_m = (wid & 1) * 64;   // 2 warps along m
    const int warp_n = (wid >> 1) * 32;  // 4 warps along n

    // global load mapping: thread covers (row = tid/2, k seg = (tid&1)*16..+15)
    const int grow = tid >> 1;
    const int gk   = (tid & 1) << 4;
    const __nv_bfloat16* pAh = g.Ah + (size_t)(bm + grow) * D_ + gk;
    const __nv_bfloat16* pAl = g.Al + (size_t)(bm + grow) * D_ + gk;
    const __nv_bfloat16* pBh = g.Wh + (size_t)(bn + grow) * D_ + gk;
    const __nv_bfloat16* pBl = g.Wl + (size_t)(bn + grow) * D_ + gk;
    char* stAh = (char*)sAh + grow * (SROW * 2) + gk * 2;
    char* stAl = (char*)sAl + grow * (SROW * 2) + gk * 2;
    char* stBh = (char*)sBh + grow * (SROW * 2) + gk * 2;
    char* stBl = (char*)sBl + grow * (SROW * 2) + gk * 2;

    float acc[4][4][4];
#pragma unroll
    for (int mt = 0; mt < 4; mt++)
#pragma unroll
        for (int nt = 0; nt < 4; nt++)
#pragma unroll
            for (int q = 0; q < 4; q++) acc[mt][nt][q] = 0.f;

    // preload chunk 0
    {
        uint4 a0 = *(const uint4*)(pAh);
        uint4 a1 = *(const uint4*)(pAh + 8);
        uint4 b0 = *(const uint4*)(pAl);
        uint4 b1 = *(const uint4*)(pAl + 8);
        uint4 c0 = *(const uint4*)(pBh);
        uint4 c1 = *(const uint4*)(pBh + 8);
        uint4 d0 = *(const uint4*)(pBl);
        uint4 d1 = *(const uint4*)(pBl + 8);
        *(uint4*)(stAh) = a0; *(uint4*)(stAh + 16) = a1;
        *(uint4*)(stAl) = b0; *(uint4*)(stAl + 16) = b1;
        *(uint4*)(stBh) = c0; *(uint4*)(stBh + 16) = c1;
        *(uint4*)(stBl) = d0; *(uint4*)(stBl + 16) = d1;
    }
    __syncthreads();

    const int fr = lane >> 2;            // 0..7 fragment row/col group
    const int fk = (lane & 3) << 1;      // 0,2,4,6

    for (int c = 0; c < D_ / 32; ++c) {
        // prefetch next chunk into registers
        uint4 nAh0, nAh1, nAl0, nAl1, nBh0, nBh1, nBl0, nBl1;
        const bool more = (c + 1 < D_ / 32);
        if (more) {
            const int off = (c + 1) * 32;
            nAh0 = *(const uint4*)(pAh + off); nAh1 = *(const uint4*)(pAh + off + 8);
            nAl0 = *(const uint4*)(pAl + off); nAl1 = *(const uint4*)(pAl + off + 8);
            nBh0 = *(const uint4*)(pBh + off); nBh1 = *(const uint4*)(pBh + off + 8);
            nBl0 = *(const uint4*)(pBl + off); nBl1 = *(const uint4*)(pBl + off + 8);
        }

#pragma unroll
        for (int ks = 0; ks < 2; ++ks) {
            const int kk = ks * 16 + fk;
            // A-hi fragments (4 m-tiles x 4 regs)
            uint32_t ah[4][4];
#pragma unroll
            for (int mt = 0; mt < 4; mt++) {
                const int r = warp_m + mt * 16 + fr;
                ah[mt][0] = lds_u32(sAh, r,     kk);
                ah[mt][1] = lds_u32(sAh, r + 8, kk);
                ah[mt][2] = lds_u32(sAh, r,     kk + 8);
                ah[mt][3] = lds_u32(sAh, r + 8, kk + 8);
            }
            // B-hi fragments (4 n-tiles x 2 regs)
            uint32_t bh[4][2];
#pragma unroll
            for (int nt = 0; nt < 4; nt++) {
                const int n = warp_n + nt * 8 + fr;
                bh[nt][0] = lds_u32(sBh, n, kk);
                bh[nt][1] = lds_u32(sBh, n, kk + 8);
            }
            // pass 1: Ah x Bh
#pragma unroll
            for (int mt = 0; mt < 4; mt++)
#pragma unroll
                for (int nt = 0; nt < 4; nt++)
                    mma16816(acc[mt][nt][0], acc[mt][nt][1], acc[mt][nt][2], acc[mt][nt][3],
                             ah[mt][0], ah[mt][1], ah[mt][2], ah[mt][3],
                             bh[nt][0], bh[nt][1]);
            // pass 2: Al x Bh
#pragma unroll
            for (int mt = 0; mt < 4; mt++) {
                const int r = warp_m + mt * 16 + fr;
                uint32_t al0 = lds_u32(sAl, r,     kk);
                uint32_t al1 = lds_u32(sAl, r + 8, kk);
                uint32_t al2 = lds_u32(sAl, r,     kk + 8);
                uint32_t al3 = lds_u32(sAl, r + 8, kk + 8);
#pragma unroll
                for (int nt = 0; nt < 4; nt++)
                    mma16816(acc[mt][nt][0], acc[mt][nt][1], acc[mt][nt][2], acc[mt][nt][3],
                             al0, al1, al2, al3, bh[nt][0], bh[nt][1]);
            }
            // pass 3: Ah x Bl
#pragma unroll
            for (int nt = 0; nt < 4; nt++) {
                const int n = warp_n + nt * 8 + fr;
                uint32_t bl0 = lds_u32(sBl, n, kk);
                uint32_t bl1 = lds_u32(sBl, n, kk + 8);
#pragma unroll
                for (int mt = 0; mt < 4; mt++)
                    mma16816(acc[mt][nt][0], acc[mt][nt][1], acc[mt][nt][2], acc[mt][nt][3],
                             ah[mt][0], ah[mt][1], ah[mt][2], ah[mt][3],
                             bl0, bl1);
            }
        }

        __syncthreads();
        if (more) {
            *(uint4*)(stAh) = nAh0; *(uint4*)(stAh + 16) = nAh1;
            *(uint4*)(stAl) = nAl0; *(uint4*)(stAl + 16) = nAl1;
            *(uint4*)(stBh) = nBh0; *(uint4*)(stBh + 16) = nBh1;
            *(uint4*)(stBl) = nBl0; *(uint4*)(stBl + 16) = nBl1;
            __syncthreads();
        }
    }

    // epilogue
#pragma unroll
    for (int mt = 0; mt < 4; mt++) {
        const int r0 = bm + warp_m + mt * 16 + fr;
#pragma unroll
        for (int nt = 0; nt < 4; nt++) {
            const int col = bn + warp_n + nt * 8 + fk;
            const float b0 = g.bias[col], b1 = g.bias[col + 1];
            float2 v0 = make_float2(acc[mt][nt][0] + b0, acc[mt][nt][1] + b1);
            float2 v1 = make_float2(acc[mt][nt][2] + b0, acc[mt][nt][3] + b1);
            *(float2*)(g.C + (size_t)r0 * D_ + col)       = v0;
            *(float2*)(g.C + (size_t)(r0 + 8) * D_ + col) = v1;
        }
    }
}

// ---------------- global-query attention (i < 16): one block per row ----------
__global__ __launch_bounds__(128) void attn_global(
    const float* __restrict__ Q, const float* __restrict__ K,
    const float* __restrict__ V, float* __restrict__ attn, float* __restrict__ ctx)
{
    const int i = blockIdx.x;
    const int h = blockIdx.y;
    const int b = blockIdx.z;
    const int tid = threadIdx.x;

    __shared__ __align__(16) float qs[HD_];
    __shared__ float p[S_];
    __shared__ float red[4];
    __shared__ float sb;
    __shared__ float cxs[HD_];

    const float* qrow = Q + ((size_t)(b * S_ + i)) * D_ + h * HD_;
    if (tid < HD_) qs[tid] = qrow[tid];
    __syncthreads();

    float lmax = -1e30f;
    for (int j = tid; j < S_; j += 128) {
        const float* krow = K + ((size_t)(b * S_ + j)) * D_ + h * HD_;
        float s = 0.f;
#pragma unroll
        for (int d = 0; d < HD_; d += 4) {
            float4 kv = *(const float4*)(krow + d);
            float4 qv = *(const float4*)(qs + d);
            s = fmaf(qv.x, kv.x, s); s = fmaf(qv.y, kv.y, s);
            s = fmaf(qv.z, kv.z, s); s = fmaf(qv.w, kv.w, s);
        }
        s *= 0.125f;
        p[j] = s;
        lmax = fmaxf(lmax, s);
    }
#pragma unroll
    for (int o = 16; o; o >>= 1) lmax = fmaxf(lmax, __shfl_xor_sync(~0u, lmax, o));
    if ((tid & 31) == 0) red[tid >> 5] = lmax;
    __syncthreads();
    if (tid == 0) sb = fmaxf(fmaxf(red[0], red[1]), fmaxf(red[2], red[3]));
    __syncthreads();
    const float m = sb;
    __syncthreads();

    float lsum = 0.f;
    for (int j = tid; j < S_; j += 128) { float e = __expf(p[j] - m); p[j] = e; lsum += e; }
#pragma unroll
    for (int o = 16; o; o >>= 1) lsum += __shfl_xor_sync(~0u, lsum, o);
    if ((tid & 31) == 0) red[tid >> 5] = lsum;
    __syncthreads();
    if (tid == 0) sb = 1.f / (red[0] + red[1] + red[2] + red[3]);
    __syncthreads();
    const float inv = sb;

    if (attn) {
        float* arow = attn + (((size_t)(b * H_ + h)) * S_ + i) * S_;
        for (int j0 = tid * 4; j0 < S_; j0 += 128 * 4) {
            float4 o4;
            o4.x = p[j0 + 0] * inv; o4.y = p[j0 + 1] * inv;
            o4.z = p[j0 + 2] * inv; o4.w = p[j0 + 3] * inv;
            *(float4*)(arow + j0) = o4;
        }
    }
    {
        const int d = tid & 63;
        const int half = tid >> 6;
        float acc = 0.f;
        for (int j = half; j < S_; j += 2)
            acc = fmaf(p[j], V[((size_t)(b * S_ + j)) * D_ + h * HD_ + d], acc);
        if (half == 1) cxs[d] = acc;
        __syncthreads();
        if (half == 0)
            ctx[((size_t)(b * S_ + i)) * D_ + h * HD_ + d] = (acc + cxs[d]) * inv;
    }
}

// ---------------- banded attention: 16 query rows per block -------------------
#define NC 96
#define KPAD 65
#define PPAD 97
#define BAND_OFF_Q  0
#define BAND_OFF_K  (16*64*4)
#define BAND_OFF_V  (BAND_OFF_K + NC*KPAD*4)
#define BAND_OFF_P  (BAND_OFF_V + NC*KPAD*4)
#define BAND_OFF_I  (BAND_OFF_P + 16*PPAD*4)
#define BAND_SMEM   (BAND_OFF_I + 64)

__global__ __launch_bounds__(256) void attn_band(
    const float* __restrict__ Q, const float* __restrict__ K,
    const float* __restrict__ V, float* __restrict__ attn, float* __restrict__ ctx)
{
    extern __shared__ __align__(16) char sm[];
    float* Qs = (float*)(sm + BAND_OFF_Q);
    float* Ks = (float*)(sm + BAND_OFF_K);
    float* Vs = (float*)(sm + BAND_OFF_V);
    float* p  = (float*)(sm + BAND_OFF_P);
    float* invs = (float*)(sm + BAND_OFF_I);

    const int i0 = GLB + blockIdx.x * 16;
    const int h  = blockIdx.y;
    const int b  = blockIdx.z;
    const int tid = threadIdx.x;

    const int blo = max(i0 - HALFW, GLB);
    const int bhi = min(i0 + 15 + HALFW, S_ - 1);
    const int nb  = bhi - blo + 1;

    {
        const int s = tid >> 4, f4 = tid & 15;
        float4 v = *(const float4*)(Q + ((size_t)(b * S_ + i0 + s)) * D_ + h * HD_ + f4 * 4);
        *(float4*)(Qs + s * 64 + f4 * 4) = v;
    }
    for (int task = tid; task < NC * 16; task += 256) {
        const int s = task >> 4, f4 = task & 15;
        float4 kv = make_float4(0.f, 0.f, 0.f, 0.f);
        float4 vv = make_float4(0.f, 0.f, 0.f, 0.f);
        int j = -1;
        if (s < GLB) j = s;
        else if (s - GLB < nb) j = blo + (s - GLB);
        if (j >= 0) {
            kv = *(const float4*)(K + ((size_t)(b * S_ + j)) * D_ + h * HD_ + f4 * 4);
            vv = *(const float4*)(V + ((size_t)(b * S_ + j)) * D_ + h * HD_ + f4 * 4);
        }
        float* kd = Ks + s * KPAD + f4 * 4;
        float* vd = Vs + s * KPAD + f4 * 4;
        kd[0] = kv.x; kd[1] = kv.y; kd[2] = kv.z; kd[3] = kv.w;
        vd[0] = vv.x; vd[1] = vv.y; vd[2] = vv.z; vd[3] = vv.w;
    }
    __syncthreads();

    for (int e = tid; e < 16 * NC; e += 256) {
        const int r = e / NC, c = e % NC;
        const int i = i0 + r;
        bool valid;
        if (c < GLB) valid = true;
        else {
            const int idx = c - GLB;
            const int j = blo + idx;
            valid = (idx < nb) && (j >= i - HALFW) && (j <= i + HALFW);
        }
        float s = 0.f;
        const float* kr = Ks + c * KPAD;
        const float* qr = Qs + r * 64;
#pragma unroll
        for (int d = 0; d < 64; ++d) s = fmaf(qr[d], kr[d], s);
        p[r * PPAD + c] = valid ? s * 0.125f : -1e30f;
    }
    __syncthreads();

    {
        const int w = tid >> 5, lane = tid & 31;
#pragma unroll
        for (int rr = 2 * w; rr <= 2 * w + 1; ++rr) {
            float m = -1e30f;
#pragma unroll
            for (int c = lane; c < NC; c += 32) m = fmaxf(m, p[rr * PPAD + c]);
#pragma unroll
            for (int o = 16; o; o >>= 1) m = fmaxf(m, __shfl_xor_sync(~0u, m, o));
            float sum = 0.f;
#pragma unroll
            for (int c = lane; c < NC; c += 32) {
                float e = __expf(p[rr * PPAD + c] - m);
                p[rr * PPAD + c] = e;
                sum += e;
            }
#pragma unroll
            for (int o = 16; o; o >>= 1) sum += __shfl_xor_sync(~0u, sum, o);
            if (lane == 0) invs[rr] = 1.f / sum;
        }
    }
    __syncthreads();

    if (attn) {
        const int w = tid >> 5, lane = tid & 31;
#pragma unroll
        for (int rr = 2 * w; rr <= 2 * w + 1; ++rr) {
            const int i = i0 + rr;
            const float inv = invs[rr];
            float* arow = attn + (((size_t)(b * H_ + h)) * S_ + i) * S_;
            if (lane < GLB) arow[lane] = p[rr * PPAD + lane] * inv;
#pragma unroll
            for (int c = GLB + lane; c < NC; c += 32) {
                const int idx = c - GLB;
                if (idx < nb) {
                    const int j = blo + idx;
                    if (j >= i - HALFW && j <= i + HALFW)
                        arow[j] = p[rr * PPAD + c] * inv;
                }
            }
        }
    }

    {
        const int r = tid >> 4, dg = tid & 15;
        float a0 = 0.f, a1 = 0.f, a2 = 0.f, a3 = 0.f;
#pragma unroll 4
        for (int c = 0; c < NC; ++c) {
            const float wgt = p[r * PPAD + c];
            const float* vr = Vs + c * KPAD + dg * 4;
            a0 = fmaf(wgt, vr[0], a0); a1 = fmaf(wgt, vr[1], a1);
            a2 = fmaf(wgt, vr[2], a2); a3 = fmaf(wgt, vr[3], a3);
        }
        const float inv = invs[r];
        const int i = i0 + r;
        float4 o4 = make_float4(a0 * inv, a1 * inv, a2 * inv, a3 * inv);
        *(float4*)(ctx + ((size_t)(b * S_ + i)) * D_ + h * HD_ + dg * 4) = o4;
    }
}

// ------------------------------- launch ---------------------------------------
extern "C" void kernel_launch(void* const* d_in, const int* in_sizes, int n_in,
                              void* d_out, int out_size)
{
    const float* query = (const float*)d_in[0];
    const float* key   = (const float*)d_in[1];
    const float* value = (const float*)d_in[2];
    const float* Wq = (const float*)d_in[3];
    const float* bq = (const float*)d_in[4];
    const float* Wk = (const float*)d_in[5];
    const float* bk = (const float*)d_in[6];
    const float* Wv = (const float*)d_in[7];
    const float* bv = (const float*)d_in[8];
    const float* Wo = (const float*)d_in[9];
    const float* bo = (const float*)d_in[10];

    float* out = (float*)d_out;

    float *Qp, *Kp, *Vp, *Cp;
    cudaGetSymbolAddress((void**)&Qp, g_Q);
    cudaGetSymbolAddress((void**)&Kp, g_K);
    cudaGetSymbolAddress((void**)&Vp, g_V);
    cudaGetSymbolAddress((void**)&Cp, g_ctx);

    __nv_bfloat16 *qh,*ql,*kh,*kl,*vh,*vl,*ch,*cl;
    __nv_bfloat16 *wqh,*wql,*wkh,*wkl,*wvh,*wvl,*woh,*wol;
    cudaGetSymbolAddress((void**)&qh, g_qh);  cudaGetSymbolAddress((void**)&ql, g_ql);
    cudaGetSymbolAddress((void**)&kh, g_kh);  cudaGetSymbolAddress((void**)&kl, g_kl);
    cudaGetSymbolAddress((void**)&vh, g_vh);  cudaGetSymbolAddress((void**)&vl, g_vl);
    cudaGetSymbolAddress((void**)&ch, g_ch);  cudaGetSymbolAddress((void**)&cl, g_cl);
    cudaGetSymbolAddress((void**)&wqh, g_wqh); cudaGetSymbolAddress((void**)&wql, g_wql);
    cudaGetSymbolAddress((void**)&wkh, g_wkh); cudaGetSymbolAddress((void**)&wkl, g_wkl);
    cudaGetSymbolAddress((void**)&wvh, g_wvh); cudaGetSymbolAddress((void**)&wvl, g_wvl);
    cudaGetSymbolAddress((void**)&woh, g_woh); cudaGetSymbolAddress((void**)&wol, g_wol);

    const size_t out_elems  = (size_t)B_ * S_ * D_;
    const size_t attn_elems = (size_t)B_ * H_ * S_ * S_;
    const bool write_attn = ((size_t)out_size >= out_elems + attn_elems);
    float* attn = write_attn ? (out + out_elems) : nullptr;

    cudaFuncSetAttribute(attn_band, cudaFuncAttributeMaxDynamicSharedMemorySize, BAND_SMEM);

    if (attn)
        cudaMemsetAsync(attn, 0, attn_elems * sizeof(float));

    // pre-convert inputs (3 x 4M) and weights (4 x 1M) to bf16 hi/lo
    {
        CvtArgs ci0{query, qh, ql}, ci1{key, kh, kl}, ci2{value, vh, vl};
        cvt_hilo<<<dim3(1024, 1, 3), 256>>>(ci0, ci1, ci2, ci2, MTOT * D_);
        CvtArgs cw0{Wq, wqh, wql}, cw1{Wk, wkh, wkl}, cw2{Wv, wvh, wvl}, cw3{Wo, woh, wol};
        cvt_hilo<<<dim3(512, 1, 4), 256>>>(cw0, cw1, cw2, cw3, D_ * D_);
    }

    GemmB bq_{qh, ql, wqh, wql, bq, Qp};
    GemmB bk_{kh, kl, wkh, wkl, bk, Kp};
    GemmB bv_{vh, vl, wvh, wvl, bv, Vp};

    dim3 gqkv(D_ / 128, MTOT / 128, 3);
    gemm_mma<<<gqkv, 256>>>(bq_, bk_, bv_);

    attn_global<<<dim3(GLB, H_, B_), 128>>>(Qp, Kp, Vp, attn, Cp);
    attn_band<<<dim3((S_ - GLB) / 16, H_, B_), 256, BAND_SMEM>>>(Qp, Kp, Vp, attn, Cp);

    // convert ctx, then output projection
    {
        CvtArgs cc{Cp, ch, cl};
        cvt_hilo<<<dim3(1024, 1, 1), 256>>>(cc, cc, cc, cc, MTOT * D_);
    }
    GemmB bo_{ch, cl, woh, wol, bo, out};
    dim3 gout(D_ / 128, MTOT / 128, 1);
    gemm_mma<<<gout, 256>>>(bo_, bo_, bo_);
}